// round 3
// baseline (speedup 1.0000x reference)
#include <cuda_runtime.h>
#include <math.h>

#define NN 4096
#define C1 256
#define C2 512
#define CHW (256*4096)

// ---------------- static scratch (no allocations allowed) ----------------
__device__ float g_xr[2*CHW];
__device__ float g_pos[CHW];
__device__ float g_bnsc[C1], g_bnsh[C1];
__device__ float g_partS[32*C2], g_partQ[32*C2];
__device__ float g_invn_s[C1], g_invn2_s[C1];
__device__ float g_invn_q[C1], g_invn2_q[C1];
__device__ float g_invn_e1[C2], g_dummy1[C2];
__device__ float g_invn_e2[C2], g_dummy2[C2];
__device__ float g_invee[C2];
__device__ float g_fsc[C2], g_fsh[C2];
__device__ float g_colabsPart[32*NN];
__device__ float g_invcol_s[NN], g_invcol_q[NN];
__device__ unsigned int g_rmax_ord;
__device__ float g_inv_rmax;
__device__ float g_ax[NN*C2];
__device__ float g_ux[NN*C2];
__device__ float g_T[C2*C2];
__device__ float g_Tpart[16*C2*C2];
__device__ float g_emb1[NN*C2];
__device__ float g_emb2[NN*C2];
__device__ float g_r2[NN*C2];
__device__ float g_y2[NN*C2];

__device__ __forceinline__ unsigned ord_of_float(float f) {
    unsigned u = __float_as_uint(f);
    return (u & 0x80000000u) ? ~u : (u | 0x80000000u);
}

// ---------------- generic SGEMM 128x128x16, 256 thr, 8x8/thr ----------------
// TA=0: A (M,K) rm ; TA=1: A (K,M) rm (A^T). TB=0: B (K,N) rm ; TB=1: B (N,K) rm.
// splitLen>0: grid.z slices of K, raw partials at C+z*M*N. else grid.z = batch.
// Requires M%128==0, N%128==0, K%16==0.
template<int TA, int TB>
__global__ void __launch_bounds__(256)
gemm_k(int M, int N, int K,
       const float* __restrict__ A, int lda, size_t sA,
       const float* __restrict__ B, int ldb, size_t sB,
       float* __restrict__ C, size_t sC,
       const float* __restrict__ ksA, const float* __restrict__ ksB,
       int splitLen, float alphaS, const float* __restrict__ alphaPtr,
       const float* __restrict__ bias,
       const float* __restrict__ addMat, int doRelu)
{
    __shared__ float As[16][128];
    __shared__ float Bs[16][128];
    const int tid = threadIdx.x;
    const int tx = tid & 15, ty = tid >> 4;
    const int n0 = blockIdx.x * 128;
    const int m0 = blockIdx.y * 128;
    const int z  = blockIdx.z;

    int k0, kEnd;
    if (splitLen > 0) { k0 = z * splitLen; kEnd = k0 + splitLen; C += (size_t)z * M * N; }
    else { k0 = 0; kEnd = K; A += (size_t)z*sA; B += (size_t)z*sB; C += (size_t)z*sC; }

    float acc[8][8];
    #pragma unroll
    for (int i=0;i<8;i++)
        #pragma unroll
        for (int j=0;j<8;j++) acc[i][j]=0.f;

    for (int kk = k0; kk < kEnd; kk += 16) {
        if (TA == 0) {
            int m = tid >> 1, k8 = (tid & 1) * 8;
            const float* src = A + (size_t)(m0+m)*lda + kk + k8;
            float4 v0 = *(const float4*)src, v1 = *(const float4*)(src+4);
            float vv[8] = {v0.x,v0.y,v0.z,v0.w,v1.x,v1.y,v1.z,v1.w};
            #pragma unroll
            for (int i=0;i<8;i++) {
                float s = ksA ? ksA[kk+k8+i] : 1.f;
                As[k8+i][m] = vv[i]*s;
            }
        } else {
            int k = tid >> 4, m8 = (tid & 15) * 8;
            const float* src = A + (size_t)(kk+k)*lda + m0 + m8;
            float s = ksA ? ksA[kk+k] : 1.f;
            float4 v0 = *(const float4*)src, v1 = *(const float4*)(src+4);
            As[k][m8+0]=v0.x*s; As[k][m8+1]=v0.y*s; As[k][m8+2]=v0.z*s; As[k][m8+3]=v0.w*s;
            As[k][m8+4]=v1.x*s; As[k][m8+5]=v1.y*s; As[k][m8+6]=v1.z*s; As[k][m8+7]=v1.w*s;
        }
        if (TB == 0) {
            int k = tid >> 4, n8 = (tid & 15) * 8;
            const float* src = B + (size_t)(kk+k)*ldb + n0 + n8;
            float s = ksB ? ksB[kk+k] : 1.f;
            float4 v0 = *(const float4*)src, v1 = *(const float4*)(src+4);
            Bs[k][n8+0]=v0.x*s; Bs[k][n8+1]=v0.y*s; Bs[k][n8+2]=v0.z*s; Bs[k][n8+3]=v0.w*s;
            Bs[k][n8+4]=v1.x*s; Bs[k][n8+5]=v1.y*s; Bs[k][n8+6]=v1.z*s; Bs[k][n8+7]=v1.w*s;
        } else {
            int n = tid >> 1, k8 = (tid & 1) * 8;
            const float* src = B + (size_t)(n0+n)*ldb + kk + k8;
            float4 v0 = *(const float4*)src, v1 = *(const float4*)(src+4);
            float vv[8] = {v0.x,v0.y,v0.z,v0.w,v1.x,v1.y,v1.z,v1.w};
            #pragma unroll
            for (int i=0;i<8;i++) {
                float s = ksB ? ksB[kk+k8+i] : 1.f;
                Bs[k8+i][n] = vv[i]*s;
            }
        }
        __syncthreads();
        #pragma unroll
        for (int k=0;k<16;k++) {
            float4 a0 = *(const float4*)&As[k][ty*4];
            float4 a1 = *(const float4*)&As[k][ty*4+64];
            float4 b0 = *(const float4*)&Bs[k][tx*4];
            float4 b1 = *(const float4*)&Bs[k][tx*4+64];
            float a[8] = {a0.x,a0.y,a0.z,a0.w,a1.x,a1.y,a1.z,a1.w};
            float b[8] = {b0.x,b0.y,b0.z,b0.w,b1.x,b1.y,b1.z,b1.w};
            #pragma unroll
            for (int i=0;i<8;i++)
                #pragma unroll
                for (int j=0;j<8;j++)
                    acc[i][j] += a[i]*b[j];
        }
        __syncthreads();
    }

    if (splitLen > 0) {
        #pragma unroll
        for (int i=0;i<8;i++) {
            int m = m0 + ty*4 + (i&3) + ((i>>2)<<6);
            #pragma unroll
            for (int j=0;j<8;j++) {
                int n = n0 + tx*4 + (j&3) + ((j>>2)<<6);
                C[(size_t)m*N + n] = acc[i][j];
            }
        }
        return;
    }
    float alpha = alphaS * (alphaPtr ? *alphaPtr : 1.f);
    #pragma unroll
    for (int i=0;i<8;i++) {
        int m = m0 + ty*4 + (i&3) + ((i>>2)<<6);
        #pragma unroll
        for (int j=0;j<8;j++) {
            int n = n0 + tx*4 + (j&3) + ((j>>2)<<6);
            float v = acc[i][j]*alpha;
            if (bias)   v += bias[n];
            if (addMat) v += addMat[(size_t)m*N + n];
            if (doRelu) v = fmaxf(v, 0.f);
            C[(size_t)m*N + n] = v;
        }
    }
}

__global__ void splitk_reduce(int S, int MN, const float* __restrict__ part,
                              float* __restrict__ C)
{
    int idx = blockIdx.x*256 + threadIdx.x;
    if (idx >= MN) return;
    float s = 0.f;
    #pragma unroll 4
    for (int z=0; z<S; z++) s += part[(size_t)z*MN + idx];
    C[idx] = s;
}

// ------------- streamed Gram stats: G = (A*sa)(B*sb)^T, never stored ---------
__global__ void __launch_bounds__(256)
gram_stats(int Nn, int Cc,
           const float* __restrict__ A, int lda, const float* __restrict__ sa,
           const float* __restrict__ Bm, int ldb, const float* __restrict__ sb,
           float* __restrict__ colAbsPart, unsigned int* __restrict__ maxOrd)
{
    __shared__ float As[16][128];
    __shared__ float Bs[16][128];
    const int tid = threadIdx.x;
    const int tx = tid & 15, ty = tid >> 4;
    const int m0 = blockIdx.x * 128;   // columns (B rows)
    const int n0 = blockIdx.y * 128;   // rows (A rows)

    float acc[8][8];
    #pragma unroll
    for (int i=0;i<8;i++)
        #pragma unroll
        for (int j=0;j<8;j++) acc[i][j]=0.f;

    for (int cc = 0; cc < Cc; cc += 16) {
        {
            int n = tid >> 1, c8 = (tid & 1)*8;
            const float* src = A + (size_t)(n0+n)*lda + cc + c8;
            float4 v0 = *(const float4*)src, v1 = *(const float4*)(src+4);
            float vv[8] = {v0.x,v0.y,v0.z,v0.w,v1.x,v1.y,v1.z,v1.w};
            #pragma unroll
            for (int i=0;i<8;i++) As[c8+i][n] = vv[i]*sa[cc+c8+i];
        }
        {
            int m = tid >> 1, c8 = (tid & 1)*8;
            const float* src = Bm + (size_t)(m0+m)*ldb + cc + c8;
            float4 v0 = *(const float4*)src, v1 = *(const float4*)(src+4);
            float vv[8] = {v0.x,v0.y,v0.z,v0.w,v1.x,v1.y,v1.z,v1.w};
            #pragma unroll
            for (int i=0;i<8;i++) Bs[c8+i][m] = vv[i]*sb[cc+c8+i];
        }
        __syncthreads();
        #pragma unroll
        for (int k=0;k<16;k++) {
            float4 a0 = *(const float4*)&As[k][ty*4];
            float4 a1 = *(const float4*)&As[k][ty*4+64];
            float4 b0 = *(const float4*)&Bs[k][tx*4];
            float4 b1 = *(const float4*)&Bs[k][tx*4+64];
            float a[8] = {a0.x,a0.y,a0.z,a0.w,a1.x,a1.y,a1.z,a1.w};
            float b[8] = {b0.x,b0.y,b0.z,b0.w,b1.x,b1.y,b1.z,b1.w};
            #pragma unroll
            for (int i=0;i<8;i++)
                #pragma unroll
                for (int j=0;j<8;j++)
                    acc[i][j] += a[i]*b[j];
        }
        __syncthreads();
    }

    if (colAbsPart) {
        __shared__ float cpart[16][128];
        #pragma unroll
        for (int j=0;j<8;j++) {
            float s = 0.f;
            #pragma unroll
            for (int i=0;i<8;i++) s += fabsf(acc[i][j]);
            cpart[ty][tx*4 + (j&3) + ((j>>2)<<6)] = s;
        }
        __syncthreads();
        if (tid < 128) {
            float s = 0.f;
            #pragma unroll
            for (int t=0;t<16;t++) s += cpart[t][tid];
            colAbsPart[(size_t)blockIdx.y*Nn + m0 + tid] = s;
        }
    }
    if (maxOrd) {
        float mx = -3.4e38f;
        #pragma unroll
        for (int i=0;i<8;i++)
            #pragma unroll
            for (int j=0;j<8;j++) mx = fmaxf(mx, acc[i][j]);
        #pragma unroll
        for (int off=16; off; off>>=1)
            mx = fmaxf(mx, __shfl_xor_sync(0xffffffffu, mx, off));
        __shared__ float wmx[8];
        if ((tid & 31) == 0) wmx[tid >> 5] = mx;
        __syncthreads();
        if (tid == 0) {
            float m2 = wmx[0];
            #pragma unroll
            for (int t=1;t<8;t++) m2 = fmaxf(m2, wmx[t]);
            atomicMax(maxOrd, ord_of_float(m2));  // max is order-independent
        }
    }
}

// ---------------- small kernels ----------------
__global__ void convbn_stats(const float* __restrict__ xr, const float* __restrict__ g,
                             const float* __restrict__ b, float* sc, float* sh)
{
    int o = blockIdx.x;
    const float* p0 = xr + (size_t)o*4096;
    const float* p1 = xr + (size_t)CHW + (size_t)o*4096;
    float s=0.f, q=0.f;
    for (int i = threadIdx.x; i < 4096; i += 256) {
        float v = p0[i]; s += v; q += v*v;
        v = p1[i];       s += v; q += v*v;
    }
    __shared__ float ss[256], sq[256];
    ss[threadIdx.x]=s; sq[threadIdx.x]=q; __syncthreads();
    for (int off=128; off; off>>=1) {
        if (threadIdx.x < off) { ss[threadIdx.x]+=ss[threadIdx.x+off]; sq[threadIdx.x]+=sq[threadIdx.x+off]; }
        __syncthreads();
    }
    if (threadIdx.x == 0) {
        float mean = ss[0]/8192.f;
        float var  = sq[0]/8192.f - mean*mean;
        float scl  = g[o]*rsqrtf(var + 1e-5f);
        sc[o] = scl; sh[o] = b[o] - mean*scl;
    }
}

__global__ void bnrelu_k(float* x, const float* sc, const float* sh) {
    int i = blockIdx.x*256 + threadIdx.x;
    int o = (i >> 12) & 255;
    x[i] = fmaxf(x[i]*sc[o] + sh[o], 0.f);
}

__global__ void pos_kernel(const float* __restrict__ x0, const float* __restrict__ mask,
                           float* __restrict__ out)
{
    int gid = blockIdx.x*256 + threadIdx.x;
    int c = gid >> 12, p = gid & 4095;
    int i = p >> 6, j = p & 63;
    const float* img = x0 + (size_t)c*4096;
    float yd = i * (511.f/63.f);
    int Y0 = min((int)yd, 511), Y1 = min(Y0+1, 511);
    float wy = yd - (float)Y0;
    float xd = j * (511.f/63.f);
    int X0 = min((int)xd, 511), X1 = min(X0+1, 511);
    float wx = xd - (float)X0;
    int Ys[2]={Y0,Y1}; float wys[2]={1.f-wy, wy};
    int Xs[2]={X0,X1}; float wxs[2]={1.f-wx, wx};
    float acc = 0.f;
    #pragma unroll
    for (int a=0;a<2;a++) {
        int Y = Ys[a];
        float yu = Y*(63.f/511.f);
        int a0 = min((int)yu, 63), a1 = min(a0+1, 63);
        float wa = yu - (float)a0;
        #pragma unroll
        for (int b=0;b<2;b++) {
            int X = Xs[b];
            float xu = X*(63.f/511.f);
            int b0 = min((int)xu, 63), b1 = min(b0+1, 63);
            float wb = xu - (float)b0;
            float v = (img[a0*64+b0]*(1.f-wb) + img[a0*64+b1]*wb)*(1.f-wa)
                    + (img[a1*64+b0]*(1.f-wb) + img[a1*64+b1]*wb)*wa;
            acc += wys[a]*wxs[b]*mask[Y*512+X]*v;
        }
    }
    out[gid] = acc;
}

__global__ void colred_part(const float* __restrict__ X, int ld, int C,
                            float* pS, float* pQ)
{
    int r0 = blockIdx.x * 128;
    int c0 = threadIdx.x, c1 = threadIdx.x + 256;
    float s0=0,q0=0,s1=0,q1=0;
    for (int r=0;r<128;r++) {
        const float* row = X + (size_t)(r0+r)*ld;
        float v = row[c0]; s0 += v; q0 += v*v;
        if (C > 256) { float w = row[c1]; s1 += w; q1 += w*w; }
    }
    pS[blockIdx.x*C + c0] = s0; pQ[blockIdx.x*C + c0] = q0;
    if (C > 256) { pS[blockIdx.x*C + c1] = s1; pQ[blockIdx.x*C + c1] = q1; }
}

// mode 0: o1=1/max(||col||,eps), o2=o1^2.  mode 1: BN scale/shift over 4096 rows.
__global__ void colred_fin(const float* pS, const float* pQ, int C, int mode,
                           const float* g, const float* b, float* o1, float* o2)
{
    int c = blockIdx.x*256 + threadIdx.x;
    if (c >= C) return;
    float S=0.f, Q=0.f;
    for (int z=0; z<32; z++) { S += pS[z*C+c]; Q += pQ[z*C+c]; }
    if (mode == 0) {
        float inv = 1.f / fmaxf(sqrtf(Q), 1e-12f);
        o1[c] = inv; o2[c] = inv*inv;
    } else {
        float mean = S*(1.f/4096.f);
        float var  = Q*(1.f/4096.f) - mean*mean;
        float sc   = g[c]*rsqrtf(var + 1e-5f);
        o1[c] = sc; o2[c] = b[c] - mean*sc;
    }
}

__global__ void colabs_fin(const float* part, float* inv) {
    int m = blockIdx.x*256 + threadIdx.x;
    float s = 0.f;
    #pragma unroll 4
    for (int z=0; z<32; z++) s += part[z*NN + m];
    inv[m] = 1.f / fmaxf(s, 1e-12f);
}

__global__ void vecmul_k(const float* a, const float* b, float* o) {
    int i = blockIdx.x*256 + threadIdx.x;
    o[i] = a[i]*b[i];
}

__global__ void init_rmax_k(unsigned int* p) { *p = 0u; }
__global__ void fin_rmax_k(const unsigned int* p, float* o) {
    unsigned u = *p;
    unsigned f = (u & 0x80000000u) ? (u & 0x7fffffffu) : ~u;
    *o = 1.f / __uint_as_float(f);
}

__global__ void bnapply_k(const float* y, const float* sc, const float* sh, float* o) {
    int i = blockIdx.x*256 + threadIdx.x;
    int c = i & 511;
    o[i] = fmaxf(y[i]*sc[c] + sh[c], 0.f);
}

// ---------------- host ----------------
#define SYMF(name, sym) float* name; { void* _p=nullptr; cudaGetSymbolAddress(&_p, sym); name=(float*)_p; }

extern "C" void kernel_launch(void* const* d_in, const int* in_sizes, int n_in,
                              void* d_out, int out_size)
{
    const float* x      = (const float*)d_in[0];
    const float* mask   = (const float*)d_in[1];
    const float* conv1w = (const float*)d_in[2];
    const float* bn1g   = (const float*)d_in[3];
    const float* bn1b   = (const float*)d_in[4];
    const float* g0aw   = (const float*)d_in[5];
    const float* g0ab   = (const float*)d_in[6];
    const float* g0uw   = (const float*)d_in[7];
    const float* g0ub   = (const float*)d_in[8];
    const float* g1aw   = (const float*)d_in[9];
    const float* g1ab   = (const float*)d_in[10];
    const float* g1uw   = (const float*)d_in[11];
    const float* g1ub   = (const float*)d_in[12];
    const float* cgw    = (const float*)d_in[13];
    const float* cgb    = (const float*)d_in[14];
    const float* cgbng  = (const float*)d_in[15];
    const float* cgbnb  = (const float*)d_in[16];
    float* out = (float*)d_out;

    SYMF(xr, g_xr)       SYMF(pos, g_pos)
    SYMF(bnsc, g_bnsc)   SYMF(bnsh, g_bnsh)
    SYMF(pS, g_partS)    SYMF(pQ, g_partQ)
    SYMF(invn_s, g_invn_s)   SYMF(invn2_s, g_invn2_s)
    SYMF(invn_q, g_invn_q)   SYMF(invn2_q, g_invn2_q)
    SYMF(invn_e1, g_invn_e1) SYMF(dum1, g_dummy1)
    SYMF(invn_e2, g_invn_e2) SYMF(dum2, g_dummy2)
    SYMF(invee, g_invee)
    SYMF(fsc, g_fsc)     SYMF(fsh, g_fsh)
    SYMF(cap, g_colabsPart)
    SYMF(invcol_s, g_invcol_s) SYMF(invcol_q, g_invcol_q)
    SYMF(ax, g_ax)       SYMF(ux, g_ux)
    SYMF(T, g_T)         SYMF(Tp, g_Tpart)
    SYMF(e1, g_emb1)     SYMF(e2, g_emb2)
    SYMF(r2, g_r2)       SYMF(y2, g_y2)
    SYMF(invr, g_inv_rmax)
    unsigned int* rmo; { void* _p=nullptr; cudaGetSymbolAddress(&_p, g_rmax_ord); rmo=(unsigned int*)_p; }

    const float* xq = xr + CHW;   // x[1] after conv/bn/relu, viewed (4096,256)

    // 1) conv1: xr[b] = conv1_w @ x[b]   (M=256,N=4096,K=512) batched z=2
    gemm_k<0,0><<<dim3(32,2,2),256>>>(256,4096,512, conv1w,512,0, x,4096,(size_t)512*4096,
        xr,(size_t)CHW, nullptr,nullptr, 0, 1.f,nullptr, nullptr,nullptr,0);
    // 2) BN train stats + apply + relu
    convbn_stats<<<256,256>>>(xr, bn1g, bn1b, bnsc, bnsh);
    bnrelu_k<<<2*CHW/256,256>>>(xr, bnsc, bnsh);
    // 3) pos_node = down(up(x0)*mask)
    pos_kernel<<<CHW/256,256>>>(xr, mask, pos);
    // 4) column norms of x_s, x_q
    colred_part<<<32,256>>>(pos, 256, 256, pS, pQ);
    colred_fin<<<1,256>>>(pS, pQ, 256, 0, nullptr,nullptr, invn_s, invn2_s);
    colred_part<<<32,256>>>(xq, 256, 256, pS, pQ);
    colred_fin<<<1,256>>>(pS, pQ, 256, 0, nullptr,nullptr, invn_q, invn2_q);

    // ---- layer 0, graph s -> emb1 ----
    gemm_k<0,1><<<dim3(4,32,1),256>>>(4096,512,256, pos,256,0, g0aw,256,0, ax,0,
        nullptr,nullptr, 0, 1.f,nullptr, g0ab,nullptr,1);
    gemm_k<0,1><<<dim3(4,32,1),256>>>(4096,512,256, pos,256,0, g0uw,256,0, ux,0,
        nullptr,nullptr, 0, 1.f,nullptr, g0ub,nullptr,1);
    gram_stats<<<dim3(32,32),256>>>(NN,256, pos,256,invn_s, pos,256,invn_s, cap, nullptr);
    colabs_fin<<<16,256>>>(cap, invcol_s);
    gemm_k<1,0><<<dim3(4,2,16),256>>>(256,512,4096, pos,256,0, ax,512,0, Tp,0,
        nullptr,invcol_s, 256, 1.f,nullptr, nullptr,nullptr,0);
    splitk_reduce<<<512,256>>>(16, 256*512, Tp, T);
    gemm_k<0,0><<<dim3(4,32,1),256>>>(4096,512,256, pos,256,0, T,512,0, e1,0,
        invn2_s,nullptr, 0, 1.f,nullptr, nullptr,ux,0);

    // ---- layer 0, graph q -> emb2 ----
    gemm_k<0,1><<<dim3(4,32,1),256>>>(4096,512,256, xq,256,0, g0aw,256,0, ax,0,
        nullptr,nullptr, 0, 1.f,nullptr, g0ab,nullptr,1);
    gemm_k<0,1><<<dim3(4,32,1),256>>>(4096,512,256, xq,256,0, g0uw,256,0, ux,0,
        nullptr,nullptr, 0, 1.f,nullptr, g0ub,nullptr,1);
    gram_stats<<<dim3(32,32),256>>>(NN,256, xq,256,invn_q, xq,256,invn_q, cap, nullptr);
    colabs_fin<<<16,256>>>(cap, invcol_q);
    gemm_k<1,0><<<dim3(4,2,16),256>>>(256,512,4096, xq,256,0, ax,512,0, Tp,0,
        nullptr,invcol_q, 256, 1.f,nullptr, nullptr,nullptr,0);
    splitk_reduce<<<512,256>>>(16, 256*512, Tp, T);
    gemm_k<0,0><<<dim3(4,32,1),256>>>(4096,512,256, xq,256,0, T,512,0, e2,0,
        invn2_q,nullptr, 0, 1.f,nullptr, nullptr,ux,0);

    // ---- R = adjacency(emb1, emb2): norms + streamed max ----
    colred_part<<<32,256>>>(e1, 512, 512, pS, pQ);
    colred_fin<<<2,256>>>(pS, pQ, 512, 0, nullptr,nullptr, invn_e1, dum1);
    colred_part<<<32,256>>>(e2, 512, 512, pS, pQ);
    colred_fin<<<2,256>>>(pS, pQ, 512, 0, nullptr,nullptr, invn_e2, dum2);
    vecmul_k<<<2,256>>>(invn_e1, invn_e2, invee);
    init_rmax_k<<<1,1>>>(rmo);
    gram_stats<<<dim3(32,32),256>>>(NN,512, e1,512,invn_e1, e2,512,invn_e2, nullptr, rmo);
    fin_rmax_k<<<1,1>>>(rmo, invr);

    // ---- cross for emb2: r2 = (1/Rmax) * (emb2*invee) @ (emb1^T emb1) ----
    gemm_k<1,0><<<dim3(4,4,16),256>>>(512,512,4096, e1,512,0, e1,512,0, Tp,0,
        nullptr,nullptr, 256, 1.f,nullptr, nullptr,nullptr,0);
    splitk_reduce<<<1024,256>>>(16, 512*512, Tp, T);
    gemm_k<0,0><<<dim3(4,32,1),256>>>(4096,512,512, e2,512,0, T,512,0, r2,0,
        invee,nullptr, 0, 1.f,invr, nullptr,nullptr,0);
    // y = emb2 @ Wl^T + r2 @ Wr^T + cg_b   (cg_w is (512,1024))
    gemm_k<0,1><<<dim3(4,32,1),256>>>(4096,512,512, e2,512,0, cgw,1024,0, y2,0,
        nullptr,nullptr, 0, 1.f,nullptr, cgb,nullptr,0);
    gemm_k<0,1><<<dim3(4,32,1),256>>>(4096,512,512, r2,512,0, cgw+512,1024,0, y2,0,
        nullptr,nullptr, 0, 1.f,nullptr, nullptr,y2,0);
    // BN1d over nodes + relu -> emb2_new (overwrite e2)
    colred_part<<<32,256>>>(y2, 512, 512, pS, pQ);
    colred_fin<<<2,256>>>(pS, pQ, 512, 1, cgbng, cgbnb, fsc, fsh);
    bnapply_k<<<NN*512/256,256>>>(y2, fsc, fsh, e2);

    // ---- layer 1 for emb2 (uses A_q), writes d_out directly ----
    gemm_k<0,1><<<dim3(4,32,1),256>>>(4096,512,512, e2,512,0, g1aw,512,0, ax,0,
        nullptr,nullptr, 0, 1.f,nullptr, g1ab,nullptr,1);
    gemm_k<0,1><<<dim3(4,32,1),256>>>(4096,512,512, e2,512,0, g1uw,512,0, ux,0,
        nullptr,nullptr, 0, 1.f,nullptr, g1ub,nullptr,1);
    gemm_k<1,0><<<dim3(4,2,16),256>>>(256,512,4096, xq,256,0, ax,512,0, Tp,0,
        nullptr,invcol_q, 256, 1.f,nullptr, nullptr,nullptr,0);
    splitk_reduce<<<512,256>>>(16, 256*512, Tp, T);
    gemm_k<0,0><<<dim3(4,32,1),256>>>(4096,512,256, xq,256,0, T,512,0, out,0,
        invn2_q,nullptr, 0, 1.f,nullptr, nullptr,ux,0);
}

// round 4
// speedup vs baseline: 1.1133x; 1.1133x over previous
#include <cuda_runtime.h>
#include <math.h>

#define NN 4096
#define C1 256
#define C2 512
#define CHW (256*4096)
#define CRP 256   // colred_part blocks

// ---------------- static scratch (no allocations allowed) ----------------
__device__ float g_xr[2*CHW];
__device__ float g_pos[CHW];
__device__ float g_bnsc[C1], g_bnsh[C1];
__device__ float g_partS[CRP*C2], g_partQ[CRP*C2];
__device__ float g_invn_s[C1], g_invn2_s[C1];
__device__ float g_invn_q[C1], g_invn2_q[C1];
__device__ float g_invn_e1[C2], g_dummy1[C2];
__device__ float g_invn_e2[C2], g_dummy2[C2];
__device__ float g_invee[C2];
__device__ float g_fsc[C2], g_fsh[C2];
__device__ float g_colabsPart[32*NN];
__device__ float g_invcol_s[NN], g_invcol_q[NN];
__device__ unsigned int g_rmax_ord;
__device__ float g_inv_rmax;
__device__ float g_ax[NN*C2];
__device__ float g_ux[NN*C2];
__device__ float g_T[C2*C2];
__device__ float g_Tpart[16*C2*C2];
__device__ float g_emb1[NN*C2];
__device__ float g_emb2[NN*C2];
__device__ float g_r2[NN*C2];
__device__ float g_y2[NN*C2];

__device__ __forceinline__ unsigned ord_of_float(float f) {
    unsigned u = __float_as_uint(f);
    return (u & 0x80000000u) ? ~u : (u | 0x80000000u);
}

// ---------------- generic SGEMM 128x128x16, double-buffered smem ----------------
// TA=0: A (M,K) rm ; TA=1: A (K,M) rm (A^T). TB=0: B (K,N) rm ; TB=1: B (N,K) rm.
// splitLen>0: grid.z slices of K, raw partials at C+z*M*N. else grid.z = batch.
// Requires M%128==0, N%128==0, K%16==0 (and splitLen%16==0).
template<int TA, int TB>
__global__ void __launch_bounds__(256)
gemm_k(int M, int N, int K,
       const float* __restrict__ A, int lda, size_t sA,
       const float* __restrict__ B, int ldb, size_t sB,
       float* __restrict__ C, size_t sC,
       const float* __restrict__ ksA, const float* __restrict__ ksB,
       int splitLen, float alphaS, const float* __restrict__ alphaPtr,
       const float* __restrict__ bias,
       const float* __restrict__ addMat, int doRelu)
{
    __shared__ float As[2][16][128];
    __shared__ float Bs[2][16][128];
    const int tid = threadIdx.x;
    const int tx = tid & 15, ty = tid >> 4;
    const int n0 = blockIdx.x * 128;
    const int m0 = blockIdx.y * 128;
    const int z  = blockIdx.z;

    int k0, kEnd;
    if (splitLen > 0) { k0 = z * splitLen; kEnd = k0 + splitLen; C += (size_t)z * M * N; }
    else { k0 = 0; kEnd = K; A += (size_t)z*sA; B += (size_t)z*sB; C += (size_t)z*sC; }

    float acc[8][8];
    #pragma unroll
    for (int i=0;i<8;i++)
        #pragma unroll
        for (int j=0;j<8;j++) acc[i][j]=0.f;

    float4 rA0, rA1, rB0, rB1;

    // prefetch of tile at kk into registers
    auto loadA = [&](int kk, float4& a0, float4& a1) {
        if (TA == 0) {
            int m = tid >> 1, k8 = (tid & 1) * 8;
            const float* src = A + (size_t)(m0+m)*lda + kk + k8;
            a0 = *(const float4*)src; a1 = *(const float4*)(src+4);
        } else {
            int k = tid >> 4, m8 = (tid & 15) * 8;
            const float* src = A + (size_t)(kk+k)*lda + m0 + m8;
            a0 = *(const float4*)src; a1 = *(const float4*)(src+4);
        }
    };
    auto loadB = [&](int kk, float4& b0, float4& b1) {
        if (TB == 0) {
            int k = tid >> 4, n8 = (tid & 15) * 8;
            const float* src = B + (size_t)(kk+k)*ldb + n0 + n8;
            b0 = *(const float4*)src; b1 = *(const float4*)(src+4);
        } else {
            int n = tid >> 1, k8 = (tid & 1) * 8;
            const float* src = B + (size_t)(n0+n)*ldb + kk + k8;
            b0 = *(const float4*)src; b1 = *(const float4*)(src+4);
        }
    };
    auto storeA = [&](int buf, int kk, const float4& a0, const float4& a1) {
        float vv[8] = {a0.x,a0.y,a0.z,a0.w,a1.x,a1.y,a1.z,a1.w};
        if (TA == 0) {
            int m = tid >> 1, k8 = (tid & 1) * 8;
            #pragma unroll
            for (int i=0;i<8;i++) {
                float s = ksA ? ksA[kk+k8+i] : 1.f;
                As[buf][k8+i][m] = vv[i]*s;
            }
        } else {
            int k = tid >> 4, m8 = (tid & 15) * 8;
            float s = ksA ? ksA[kk+k] : 1.f;
            #pragma unroll
            for (int i=0;i<8;i++) As[buf][k][m8+i] = vv[i]*s;
        }
    };
    auto storeB = [&](int buf, int kk, const float4& b0, const float4& b1) {
        float vv[8] = {b0.x,b0.y,b0.z,b0.w,b1.x,b1.y,b1.z,b1.w};
        if (TB == 0) {
            int k = tid >> 4, n8 = (tid & 15) * 8;
            float s = ksB ? ksB[kk+k] : 1.f;
            #pragma unroll
            for (int i=0;i<8;i++) Bs[buf][k][n8+i] = vv[i]*s;
        } else {
            int n = tid >> 1, k8 = (tid & 1) * 8;
            #pragma unroll
            for (int i=0;i<8;i++) {
                float s = ksB ? ksB[kk+k8+i] : 1.f;
                Bs[buf][k8+i][n] = vv[i]*s;
            }
        }
    };

    loadA(k0, rA0, rA1); loadB(k0, rB0, rB1);
    storeA(0, k0, rA0, rA1); storeB(0, k0, rB0, rB1);
    __syncthreads();

    int buf = 0;
    for (int kk = k0; kk < kEnd; kk += 16) {
        const bool hasNext = (kk + 16) < kEnd;
        if (hasNext) { loadA(kk+16, rA0, rA1); loadB(kk+16, rB0, rB1); }
        #pragma unroll
        for (int k=0;k<16;k++) {
            float4 a0 = *(const float4*)&As[buf][k][ty*4];
            float4 a1 = *(const float4*)&As[buf][k][ty*4+64];
            float4 b0 = *(const float4*)&Bs[buf][k][tx*4];
            float4 b1 = *(const float4*)&Bs[buf][k][tx*4+64];
            float a[8] = {a0.x,a0.y,a0.z,a0.w,a1.x,a1.y,a1.z,a1.w};
            float b[8] = {b0.x,b0.y,b0.z,b0.w,b1.x,b1.y,b1.z,b1.w};
            #pragma unroll
            for (int i=0;i<8;i++)
                #pragma unroll
                for (int j=0;j<8;j++)
                    acc[i][j] += a[i]*b[j];
        }
        if (hasNext) {
            storeA(buf^1, kk+16, rA0, rA1);
            storeB(buf^1, kk+16, rB0, rB1);
            __syncthreads();
            buf ^= 1;
        }
    }

    if (splitLen > 0) {
        #pragma unroll
        for (int i=0;i<8;i++) {
            int m = m0 + ty*4 + (i&3) + ((i>>2)<<6);
            #pragma unroll
            for (int j=0;j<8;j++) {
                int n = n0 + tx*4 + (j&3) + ((j>>2)<<6);
                C[(size_t)m*N + n] = acc[i][j];
            }
        }
        return;
    }
    float alpha = alphaS * (alphaPtr ? *alphaPtr : 1.f);
    #pragma unroll
    for (int i=0;i<8;i++) {
        int m = m0 + ty*4 + (i&3) + ((i>>2)<<6);
        #pragma unroll
        for (int j=0;j<8;j++) {
            int n = n0 + tx*4 + (j&3) + ((j>>2)<<6);
            float v = acc[i][j]*alpha;
            if (bias)   v += bias[n];
            if (addMat) v += addMat[(size_t)m*N + n];
            if (doRelu) v = fmaxf(v, 0.f);
            C[(size_t)m*N + n] = v;
        }
    }
}

__global__ void splitk_reduce(int S, int MN, const float* __restrict__ part,
                              float* __restrict__ C)
{
    int idx = blockIdx.x*256 + threadIdx.x;
    if (idx >= MN) return;
    float s = 0.f;
    #pragma unroll 4
    for (int z=0; z<S; z++) s += part[(size_t)z*MN + idx];
    C[idx] = s;
}

// ------------- streamed Gram stats: G = (A*sa)(B*sb)^T, never stored ---------
__global__ void __launch_bounds__(256)
gram_stats(int Nn, int Cc,
           const float* __restrict__ A, int lda, const float* __restrict__ sa,
           const float* __restrict__ Bm, int ldb, const float* __restrict__ sb,
           float* __restrict__ colAbsPart, unsigned int* __restrict__ maxOrd)
{
    __shared__ float As[2][16][128];
    __shared__ float Bs[2][16][128];
    const int tid = threadIdx.x;
    const int tx = tid & 15, ty = tid >> 4;
    const int m0 = blockIdx.x * 128;   // columns (B rows)
    const int n0 = blockIdx.y * 128;   // rows (A rows)
    const int nA = tid >> 1, c8 = (tid & 1)*8;

    float acc[8][8];
    #pragma unroll
    for (int i=0;i<8;i++)
        #pragma unroll
        for (int j=0;j<8;j++) acc[i][j]=0.f;

    float4 rA0, rA1, rB0, rB1;
    auto loadT = [&](int cc) {
        const float* srcA = A  + (size_t)(n0+nA)*lda + cc + c8;
        const float* srcB = Bm + (size_t)(m0+nA)*ldb + cc + c8;
        rA0 = *(const float4*)srcA; rA1 = *(const float4*)(srcA+4);
        rB0 = *(const float4*)srcB; rB1 = *(const float4*)(srcB+4);
    };
    auto storeT = [&](int buf, int cc) {
        float va[8] = {rA0.x,rA0.y,rA0.z,rA0.w,rA1.x,rA1.y,rA1.z,rA1.w};
        float vb[8] = {rB0.x,rB0.y,rB0.z,rB0.w,rB1.x,rB1.y,rB1.z,rB1.w};
        #pragma unroll
        for (int i=0;i<8;i++) {
            As[buf][c8+i][nA] = va[i]*sa[cc+c8+i];
            Bs[buf][c8+i][nA] = vb[i]*sb[cc+c8+i];
        }
    };

    loadT(0); storeT(0, 0);
    __syncthreads();

    int buf = 0;
    for (int cc = 0; cc < Cc; cc += 16) {
        const bool hasNext = (cc + 16) < Cc;
        if (hasNext) loadT(cc+16);
        #pragma unroll
        for (int k=0;k<16;k++) {
            float4 a0 = *(const float4*)&As[buf][k][ty*4];
            float4 a1 = *(const float4*)&As[buf][k][ty*4+64];
            float4 b0 = *(const float4*)&Bs[buf][k][tx*4];
            float4 b1 = *(const float4*)&Bs[buf][k][tx*4+64];
            float a[8] = {a0.x,a0.y,a0.z,a0.w,a1.x,a1.y,a1.z,a1.w};
            float b[8] = {b0.x,b0.y,b0.z,b0.w,b1.x,b1.y,b1.z,b1.w};
            #pragma unroll
            for (int i=0;i<8;i++)
                #pragma unroll
                for (int j=0;j<8;j++)
                    acc[i][j] += a[i]*b[j];
        }
        if (hasNext) {
            storeT(buf^1, cc+16);
            __syncthreads();
            buf ^= 1;
        }
    }

    if (colAbsPart) {
        __shared__ float cpart[16][128];
        __syncthreads();
        #pragma unroll
        for (int j=0;j<8;j++) {
            float s = 0.f;
            #pragma unroll
            for (int i=0;i<8;i++) s += fabsf(acc[i][j]);
            cpart[ty][tx*4 + (j&3) + ((j>>2)<<6)] = s;
        }
        __syncthreads();
        if (tid < 128) {
            float s = 0.f;
            #pragma unroll
            for (int t=0;t<16;t++) s += cpart[t][tid];
            colAbsPart[(size_t)blockIdx.y*Nn + m0 + tid] = s;
        }
    }
    if (maxOrd) {
        float mx = -3.4e38f;
        #pragma unroll
        for (int i=0;i<8;i++)
            #pragma unroll
            for (int j=0;j<8;j++) mx = fmaxf(mx, acc[i][j]);
        #pragma unroll
        for (int off=16; off; off>>=1)
            mx = fmaxf(mx, __shfl_xor_sync(0xffffffffu, mx, off));
        __shared__ float wmx[8];
        if ((tid & 31) == 0) wmx[tid >> 5] = mx;
        __syncthreads();
        if (tid == 0) {
            float m2 = wmx[0];
            #pragma unroll
            for (int t=1;t<8;t++) m2 = fmaxf(m2, wmx[t]);
            atomicMax(maxOrd, ord_of_float(m2));  // max is order-independent
        }
    }
}

// ---------------- small kernels ----------------
__global__ void convbn_stats(const float* __restrict__ xr, const float* __restrict__ g,
                             const float* __restrict__ b, float* sc, float* sh)
{
    int o = blockIdx.x;
    const float* p0 = xr + (size_t)o*4096;
    const float* p1 = xr + (size_t)CHW + (size_t)o*4096;
    float s=0.f, q=0.f;
    for (int i = threadIdx.x; i < 4096; i += 256) {
        float v = p0[i]; s += v; q += v*v;
        v = p1[i];       s += v; q += v*v;
    }
    __shared__ float ss[256], sq[256];
    ss[threadIdx.x]=s; sq[threadIdx.x]=q; __syncthreads();
    for (int off=128; off; off>>=1) {
        if (threadIdx.x < off) { ss[threadIdx.x]+=ss[threadIdx.x+off]; sq[threadIdx.x]+=sq[threadIdx.x+off]; }
        __syncthreads();
    }
    if (threadIdx.x == 0) {
        float mean = ss[0]/8192.f;
        float var  = sq[0]/8192.f - mean*mean;
        float scl  = g[o]*rsqrtf(var + 1e-5f);
        sc[o] = scl; sh[o] = b[o] - mean*scl;
    }
}

__global__ void bnrelu_k(float* x, const float* sc, const float* sh) {
    int i = blockIdx.x*256 + threadIdx.x;
    int o = (i >> 12) & 255;
    x[i] = fmaxf(x[i]*sc[o] + sh[o], 0.f);
}

__global__ void pos_kernel(const float* __restrict__ x0, const float* __restrict__ mask,
                           float* __restrict__ out)
{
    int gid = blockIdx.x*256 + threadIdx.x;
    int c = gid >> 12, p = gid & 4095;
    int i = p >> 6, j = p & 63;
    const float* img = x0 + (size_t)c*4096;
    float yd = i * (511.f/63.f);
    int Y0 = min((int)yd, 511), Y1 = min(Y0+1, 511);
    float wy = yd - (float)Y0;
    float xd = j * (511.f/63.f);
    int X0 = min((int)xd, 511), X1 = min(X0+1, 511);
    float wx = xd - (float)X0;
    int Ys[2]={Y0,Y1}; float wys[2]={1.f-wy, wy};
    int Xs[2]={X0,X1}; float wxs[2]={1.f-wx, wx};
    float acc = 0.f;
    #pragma unroll
    for (int a=0;a<2;a++) {
        int Y = Ys[a];
        float yu = Y*(63.f/511.f);
        int a0 = min((int)yu, 63), a1 = min(a0+1, 63);
        float wa = yu - (float)a0;
        #pragma unroll
        for (int b=0;b<2;b++) {
            int X = Xs[b];
            float xu = X*(63.f/511.f);
            int b0 = min((int)xu, 63), b1 = min(b0+1, 63);
            float wb = xu - (float)b0;
            float v = (img[a0*64+b0]*(1.f-wb) + img[a0*64+b1]*wb)*(1.f-wa)
                    + (img[a1*64+b0]*(1.f-wb) + img[a1*64+b1]*wb)*wa;
            acc += wys[a]*wxs[b]*mask[Y*512+X]*v;
        }
    }
    out[gid] = acc;
}

__global__ void colred_part(const float* __restrict__ X, int ld, int C,
                            float* __restrict__ pS, float* __restrict__ pQ)
{
    int r0 = blockIdx.x * (NN/CRP);       // 16 rows per block
    int c0 = threadIdx.x, c1 = threadIdx.x + 256;
    float s0=0,q0=0,s1=0,q1=0;
    #pragma unroll 4
    for (int r=0;r<NN/CRP;r++) {
        const float* row = X + (size_t)(r0+r)*ld;
        float v = row[c0]; s0 += v; q0 += v*v;
        if (C > 256) { float w = row[c1]; s1 += w; q1 += w*w; }
    }
    pS[blockIdx.x*C + c0] = s0; pQ[blockIdx.x*C + c0] = q0;
    if (C > 256) { pS[blockIdx.x*C + c1] = s1; pQ[blockIdx.x*C + c1] = q1; }
}

// mode 0: o1=1/max(||col||,eps), o2=o1^2.  mode 1: BN scale/shift over 4096 rows.
__global__ void colred_fin(const float* __restrict__ pS, const float* __restrict__ pQ,
                           int C, int mode,
                           const float* g, const float* b, float* o1, float* o2)
{
    int c = blockIdx.x*256 + threadIdx.x;
    if (c >= C) return;
    float S=0.f, Q=0.f;
    #pragma unroll 4
    for (int z=0; z<CRP; z++) { S += pS[z*C+c]; Q += pQ[z*C+c]; }
    if (mode == 0) {
        float inv = 1.f / fmaxf(sqrtf(Q), 1e-12f);
        o1[c] = inv; o2[c] = inv*inv;
    } else {
        float mean = S*(1.f/4096.f);
        float var  = Q*(1.f/4096.f) - mean*mean;
        float sc   = g[c]*rsqrtf(var + 1e-5f);
        o1[c] = sc; o2[c] = b[c] - mean*sc;
    }
}

__global__ void colabs_fin(const float* __restrict__ part, float* __restrict__ inv) {
    int m = blockIdx.x*256 + threadIdx.x;
    float s = 0.f;
    #pragma unroll 4
    for (int z=0; z<32; z++) s += part[z*NN + m];
    inv[m] = 1.f / fmaxf(s, 1e-12f);
}

__global__ void vecmul_k(const float* a, const float* b, float* o) {
    int i = blockIdx.x*256 + threadIdx.x;
    o[i] = a[i]*b[i];
}

__global__ void init_rmax_k(unsigned int* p) { *p = 0u; }
__global__ void fin_rmax_k(const unsigned int* p, float* o) {
    unsigned u = *p;
    unsigned f = (u & 0x80000000u) ? (u & 0x7fffffffu) : ~u;
    *o = 1.f / __uint_as_float(f);
}

__global__ void bnapply_k(const float* y, const float* sc, const float* sh, float* o) {
    int i = blockIdx.x*256 + threadIdx.x;
    int c = i & 511;
    o[i] = fmaxf(y[i]*sc[c] + sh[c], 0.f);
}

// ---------------- host ----------------
#define SYMF(name, sym) float* name; { void* _p=nullptr; cudaGetSymbolAddress(&_p, sym); name=(float*)_p; }

extern "C" void kernel_launch(void* const* d_in, const int* in_sizes, int n_in,
                              void* d_out, int out_size)
{
    const float* x      = (const float*)d_in[0];
    const float* mask   = (const float*)d_in[1];
    const float* conv1w = (const float*)d_in[2];
    const float* bn1g   = (const float*)d_in[3];
    const float* bn1b   = (const float*)d_in[4];
    const float* g0aw   = (const float*)d_in[5];
    const float* g0ab   = (const float*)d_in[6];
    const float* g0uw   = (const float*)d_in[7];
    const float* g0ub   = (const float*)d_in[8];
    const float* g1aw   = (const float*)d_in[9];
    const float* g1ab   = (const float*)d_in[10];
    const float* g1uw   = (const float*)d_in[11];
    const float* g1ub   = (const float*)d_in[12];
    const float* cgw    = (const float*)d_in[13];
    const float* cgb    = (const float*)d_in[14];
    const float* cgbng  = (const float*)d_in[15];
    const float* cgbnb  = (const float*)d_in[16];
    float* out = (float*)d_out;

    SYMF(xr, g_xr)       SYMF(pos, g_pos)
    SYMF(bnsc, g_bnsc)   SYMF(bnsh, g_bnsh)
    SYMF(pS, g_partS)    SYMF(pQ, g_partQ)
    SYMF(invn_s, g_invn_s)   SYMF(invn2_s, g_invn2_s)
    SYMF(invn_q, g_invn_q)   SYMF(invn2_q, g_invn2_q)
    SYMF(invn_e1, g_invn_e1) SYMF(dum1, g_dummy1)
    SYMF(invn_e2, g_invn_e2) SYMF(dum2, g_dummy2)
    SYMF(invee, g_invee)
    SYMF(fsc, g_fsc)     SYMF(fsh, g_fsh)
    SYMF(cap, g_colabsPart)
    SYMF(invcol_s, g_invcol_s) SYMF(invcol_q, g_invcol_q)
    SYMF(ax, g_ax)       SYMF(ux, g_ux)
    SYMF(T, g_T)         SYMF(Tp, g_Tpart)
    SYMF(e1, g_emb1)     SYMF(e2, g_emb2)
    SYMF(r2, g_r2)       SYMF(y2, g_y2)
    SYMF(invr, g_inv_rmax)
    unsigned int* rmo; { void* _p=nullptr; cudaGetSymbolAddress(&_p, g_rmax_ord); rmo=(unsigned int*)_p; }

    const float* xq = xr + CHW;   // x[1] after conv/bn/relu, viewed (4096,256)

    // 1) conv1: xr[b] = conv1_w @ x[b]   (M=256,N=4096,K=512) batched z=2
    gemm_k<0,0><<<dim3(32,2,2),256>>>(256,4096,512, conv1w,512,0, x,4096,(size_t)512*4096,
        xr,(size_t)CHW, nullptr,nullptr, 0, 1.f,nullptr, nullptr,nullptr,0);
    // 2) BN train stats + apply + relu
    convbn_stats<<<256,256>>>(xr, bn1g, bn1b, bnsc, bnsh);
    bnrelu_k<<<2*CHW/256,256>>>(xr, bnsc, bnsh);
    // 3) pos_node = down(up(x0)*mask)
    pos_kernel<<<CHW/256,256>>>(xr, mask, pos);
    // 4) column norms of x_s, x_q
    colred_part<<<CRP,256>>>(pos, 256, 256, pS, pQ);
    colred_fin<<<1,256>>>(pS, pQ, 256, 0, nullptr,nullptr, invn_s, invn2_s);
    colred_part<<<CRP,256>>>(xq, 256, 256, pS, pQ);
    colred_fin<<<1,256>>>(pS, pQ, 256, 0, nullptr,nullptr, invn_q, invn2_q);

    // ---- layer 0, graph s -> emb1 ----
    gemm_k<0,1><<<dim3(4,32,1),256>>>(4096,512,256, pos,256,0, g0aw,256,0, ax,0,
        nullptr,nullptr, 0, 1.f,nullptr, g0ab,nullptr,1);
    gemm_k<0,1><<<dim3(4,32,1),256>>>(4096,512,256, pos,256,0, g0uw,256,0, ux,0,
        nullptr,nullptr, 0, 1.f,nullptr, g0ub,nullptr,1);
    gram_stats<<<dim3(32,32),256>>>(NN,256, pos,256,invn_s, pos,256,invn_s, cap, nullptr);
    colabs_fin<<<16,256>>>(cap, invcol_s);
    gemm_k<1,0><<<dim3(4,2,16),256>>>(256,512,4096, pos,256,0, ax,512,0, Tp,0,
        nullptr,invcol_s, 256, 1.f,nullptr, nullptr,nullptr,0);
    splitk_reduce<<<512,256>>>(16, 256*512, Tp, T);
    gemm_k<0,0><<<dim3(4,32,1),256>>>(4096,512,256, pos,256,0, T,512,0, e1,0,
        invn2_s,nullptr, 0, 1.f,nullptr, nullptr,ux,0);

    // ---- layer 0, graph q -> emb2 ----
    gemm_k<0,1><<<dim3(4,32,1),256>>>(4096,512,256, xq,256,0, g0aw,256,0, ax,0,
        nullptr,nullptr, 0, 1.f,nullptr, g0ab,nullptr,1);
    gemm_k<0,1><<<dim3(4,32,1),256>>>(4096,512,256, xq,256,0, g0uw,256,0, ux,0,
        nullptr,nullptr, 0, 1.f,nullptr, g0ub,nullptr,1);
    gram_stats<<<dim3(32,32),256>>>(NN,256, xq,256,invn_q, xq,256,invn_q, cap, nullptr);
    colabs_fin<<<16,256>>>(cap, invcol_q);
    gemm_k<1,0><<<dim3(4,2,16),256>>>(256,512,4096, xq,256,0, ax,512,0, Tp,0,
        nullptr,invcol_q, 256, 1.f,nullptr, nullptr,nullptr,0);
    splitk_reduce<<<512,256>>>(16, 256*512, Tp, T);
    gemm_k<0,0><<<dim3(4,32,1),256>>>(4096,512,256, xq,256,0, T,512,0, e2,0,
        invn2_q,nullptr, 0, 1.f,nullptr, nullptr,ux,0);

    // ---- R = adjacency(emb1, emb2): norms + streamed max ----
    colred_part<<<CRP,256>>>(e1, 512, 512, pS, pQ);
    colred_fin<<<2,256>>>(pS, pQ, 512, 0, nullptr,nullptr, invn_e1, dum1);
    colred_part<<<CRP,256>>>(e2, 512, 512, pS, pQ);
    colred_fin<<<2,256>>>(pS, pQ, 512, 0, nullptr,nullptr, invn_e2, dum2);
    vecmul_k<<<2,256>>>(invn_e1, invn_e2, invee);
    init_rmax_k<<<1,1>>>(rmo);
    gram_stats<<<dim3(32,32),256>>>(NN,512, e1,512,invn_e1, e2,512,invn_e2, nullptr, rmo);
    fin_rmax_k<<<1,1>>>(rmo, invr);

    // ---- cross for emb2: r2 = (1/Rmax) * (emb2*invee) @ (emb1^T emb1) ----
    gemm_k<1,0><<<dim3(4,4,16),256>>>(512,512,4096, e1,512,0, e1,512,0, Tp,0,
        nullptr,nullptr, 256, 1.f,nullptr, nullptr,nullptr,0);
    splitk_reduce<<<1024,256>>>(16, 512*512, Tp, T);
    gemm_k<0,0><<<dim3(4,32,1),256>>>(4096,512,512, e2,512,0, T,512,0, r2,0,
        invee,nullptr, 0, 1.f,invr, nullptr,nullptr,0);
    // y = emb2 @ Wl^T + r2 @ Wr^T + cg_b   (cg_w is (512,1024))
    gemm_k<0,1><<<dim3(4,32,1),256>>>(4096,512,512, e2,512,0, cgw,1024,0, y2,0,
        nullptr,nullptr, 0, 1.f,nullptr, cgb,nullptr,0);
    gemm_k<0,1><<<dim3(4,32,1),256>>>(4096,512,512, r2,512,0, cgw+512,1024,0, y2,0,
        nullptr,nullptr, 0, 1.f,nullptr, nullptr,y2,0);
    // BN1d over nodes + relu -> emb2_new (overwrite e2)
    colred_part<<<CRP,256>>>(y2, 512, 512, pS, pQ);
    colred_fin<<<2,256>>>(pS, pQ, 512, 1, cgbng, cgbnb, fsc, fsh);
    bnapply_k<<<NN*512/256,256>>>(y2, fsc, fsh, e2);

    // ---- layer 1 for emb2 (uses A_q), writes d_out directly ----
    gemm_k<0,1><<<dim3(4,32,1),256>>>(4096,512,512, e2,512,0, g1aw,512,0, ax,0,
        nullptr,nullptr, 0, 1.f,nullptr, g1ab,nullptr,1);
    gemm_k<0,1><<<dim3(4,32,1),256>>>(4096,512,512, e2,512,0, g1uw,512,0, ux,0,
        nullptr,nullptr, 0, 1.f,nullptr, g1ub,nullptr,1);
    gemm_k<1,0><<<dim3(4,2,16),256>>>(256,512,4096, xq,256,0, ax,512,0, Tp,0,
        nullptr,invcol_q, 256, 1.f,nullptr, nullptr,nullptr,0);
    splitk_reduce<<<512,256>>>(16, 256*512, Tp, T);
    gemm_k<0,0><<<dim3(4,32,1),256>>>(4096,512,256, xq,256,0, T,512,0, out,0,
        invn2_q,nullptr, 0, 1.f,nullptr, nullptr,ux,0);
}

// round 5
// speedup vs baseline: 1.3408x; 1.2044x over previous
#include <cuda_runtime.h>
#include <math.h>

#define NN 4096
#define C1 256
#define C2 512
#define CHW (256*4096)
#define CRP 256   // colred_part blocks
#define GPAD 136  // smem row pitch for mma tiles (conflict-free fragment loads)

// ---------------- static scratch (no allocations allowed) ----------------
__device__ float g_xr[2*CHW];
__device__ float g_pos[CHW];
__device__ float g_bnsc[C1], g_bnsh[C1];
__device__ float g_partS[CRP*C2], g_partQ[CRP*C2];
__device__ float g_invn_s[C1], g_invn2_s[C1];
__device__ float g_invn_q[C1], g_invn2_q[C1];
__device__ float g_invn_e1[C2], g_dummy1[C2];
__device__ float g_invn_e2[C2], g_dummy2[C2];
__device__ float g_invee[C2];
__device__ float g_fsc[C2], g_fsh[C2];
__device__ float g_colabsPart[32*NN];
__device__ float g_invcol_s[NN], g_invcol_q[NN];
__device__ unsigned int g_rmax_ord;
__device__ float g_inv_rmax;
__device__ float g_ax[NN*C2];
__device__ float g_ux[NN*C2];
__device__ float g_T[C2*C2];
__device__ float g_Tpart[16*C2*C2];
__device__ float g_emb1[NN*C2];
__device__ float g_emb2[NN*C2];
__device__ float g_r2[NN*C2];
__device__ float g_y2[NN*C2];

__device__ __forceinline__ unsigned ord_of_float(float f) {
    unsigned u = __float_as_uint(f);
    return (u & 0x80000000u) ? ~u : (u | 0x80000000u);
}
__device__ __forceinline__ unsigned f2tf32(float v) {
    unsigned r; asm("cvt.rna.tf32.f32 %0, %1;" : "=r"(r) : "f"(v)); return r;
}
__device__ __forceinline__ void mma_tf32(float* d, const unsigned* a, const unsigned* b) {
    asm volatile("mma.sync.aligned.m16n8k8.row.col.f32.tf32.tf32.f32 "
        "{%0,%1,%2,%3}, {%4,%5,%6,%7}, {%8,%9}, {%0,%1,%2,%3};"
        : "+f"(d[0]), "+f"(d[1]), "+f"(d[2]), "+f"(d[3])
        : "r"(a[0]), "r"(a[1]), "r"(a[2]), "r"(a[3]), "r"(b[0]), "r"(b[1]));
}

// ---------------- generic SGEMM 128x128x16, double-buffered smem ----------------
// TA=0: A (M,K) rm ; TA=1: A (K,M) rm (A^T). TB=0: B (K,N) rm ; TB=1: B (N,K) rm.
// splitLen>0: grid.z slices of K, raw partials at C+z*M*N. else grid.z = batch.
// Requires M%128==0, N%128==0, K%16==0 (and splitLen%16==0).
template<int TA, int TB>
__global__ void __launch_bounds__(256)
gemm_k(int M, int N, int K,
       const float* __restrict__ A, int lda, size_t sA,
       const float* __restrict__ B, int ldb, size_t sB,
       float* __restrict__ C, size_t sC,
       const float* __restrict__ ksA, const float* __restrict__ ksB,
       int splitLen, float alphaS, const float* __restrict__ alphaPtr,
       const float* __restrict__ bias,
       const float* __restrict__ addMat, int doRelu)
{
    __shared__ float As[2][16][128];
    __shared__ float Bs[2][16][128];
    const int tid = threadIdx.x;
    const int tx = tid & 15, ty = tid >> 4;
    const int n0 = blockIdx.x * 128;
    const int m0 = blockIdx.y * 128;
    const int z  = blockIdx.z;

    int k0, kEnd;
    if (splitLen > 0) { k0 = z * splitLen; kEnd = k0 + splitLen; C += (size_t)z * M * N; }
    else { k0 = 0; kEnd = K; A += (size_t)z*sA; B += (size_t)z*sB; C += (size_t)z*sC; }

    float acc[8][8];
    #pragma unroll
    for (int i=0;i<8;i++)
        #pragma unroll
        for (int j=0;j<8;j++) acc[i][j]=0.f;

    float4 rA0, rA1, rB0, rB1;

    auto loadA = [&](int kk, float4& a0, float4& a1) {
        if (TA == 0) {
            int m = tid >> 1, k8 = (tid & 1) * 8;
            const float* src = A + (size_t)(m0+m)*lda + kk + k8;
            a0 = *(const float4*)src; a1 = *(const float4*)(src+4);
        } else {
            int k = tid >> 4, m8 = (tid & 15) * 8;
            const float* src = A + (size_t)(kk+k)*lda + m0 + m8;
            a0 = *(const float4*)src; a1 = *(const float4*)(src+4);
        }
    };
    auto loadB = [&](int kk, float4& b0, float4& b1) {
        if (TB == 0) {
            int k = tid >> 4, n8 = (tid & 15) * 8;
            const float* src = B + (size_t)(kk+k)*ldb + n0 + n8;
            b0 = *(const float4*)src; b1 = *(const float4*)(src+4);
        } else {
            int n = tid >> 1, k8 = (tid & 1) * 8;
            const float* src = B + (size_t)(n0+n)*ldb + kk + k8;
            b0 = *(const float4*)src; b1 = *(const float4*)(src+4);
        }
    };
    auto storeA = [&](int buf, int kk, const float4& a0, const float4& a1) {
        float vv[8] = {a0.x,a0.y,a0.z,a0.w,a1.x,a1.y,a1.z,a1.w};
        if (TA == 0) {
            int m = tid >> 1, k8 = (tid & 1) * 8;
            #pragma unroll
            for (int i=0;i<8;i++) {
                float s = ksA ? ksA[kk+k8+i] : 1.f;
                As[buf][k8+i][m] = vv[i]*s;
            }
        } else {
            int k = tid >> 4, m8 = (tid & 15) * 8;
            float s = ksA ? ksA[kk+k] : 1.f;
            #pragma unroll
            for (int i=0;i<8;i++) As[buf][k][m8+i] = vv[i]*s;
        }
    };
    auto storeB = [&](int buf, int kk, const float4& b0, const float4& b1) {
        float vv[8] = {b0.x,b0.y,b0.z,b0.w,b1.x,b1.y,b1.z,b1.w};
        if (TB == 0) {
            int k = tid >> 4, n8 = (tid & 15) * 8;
            float s = ksB ? ksB[kk+k] : 1.f;
            #pragma unroll
            for (int i=0;i<8;i++) Bs[buf][k][n8+i] = vv[i]*s;
        } else {
            int n = tid >> 1, k8 = (tid & 1) * 8;
            #pragma unroll
            for (int i=0;i<8;i++) {
                float s = ksB ? ksB[kk+k8+i] : 1.f;
                Bs[buf][k8+i][n] = vv[i]*s;
            }
        }
    };

    loadA(k0, rA0, rA1); loadB(k0, rB0, rB1);
    storeA(0, k0, rA0, rA1); storeB(0, k0, rB0, rB1);
    __syncthreads();

    int buf = 0;
    for (int kk = k0; kk < kEnd; kk += 16) {
        const bool hasNext = (kk + 16) < kEnd;
        if (hasNext) { loadA(kk+16, rA0, rA1); loadB(kk+16, rB0, rB1); }
        #pragma unroll
        for (int k=0;k<16;k++) {
            float4 a0 = *(const float4*)&As[buf][k][ty*4];
            float4 a1 = *(const float4*)&As[buf][k][ty*4+64];
            float4 b0 = *(const float4*)&Bs[buf][k][tx*4];
            float4 b1 = *(const float4*)&Bs[buf][k][tx*4+64];
            float a[8] = {a0.x,a0.y,a0.z,a0.w,a1.x,a1.y,a1.z,a1.w};
            float b[8] = {b0.x,b0.y,b0.z,b0.w,b1.x,b1.y,b1.z,b1.w};
            #pragma unroll
            for (int i=0;i<8;i++)
                #pragma unroll
                for (int j=0;j<8;j++)
                    acc[i][j] += a[i]*b[j];
        }
        if (hasNext) {
            storeA(buf^1, kk+16, rA0, rA1);
            storeB(buf^1, kk+16, rB0, rB1);
            __syncthreads();
            buf ^= 1;
        }
    }

    if (splitLen > 0) {
        #pragma unroll
        for (int i=0;i<8;i++) {
            int m = m0 + ty*4 + (i&3) + ((i>>2)<<6);
            #pragma unroll
            for (int j=0;j<8;j++) {
                int n = n0 + tx*4 + (j&3) + ((j>>2)<<6);
                C[(size_t)m*N + n] = acc[i][j];
            }
        }
        return;
    }
    float alpha = alphaS * (alphaPtr ? *alphaPtr : 1.f);
    #pragma unroll
    for (int i=0;i<8;i++) {
        int m = m0 + ty*4 + (i&3) + ((i>>2)<<6);
        #pragma unroll
        for (int j=0;j<8;j++) {
            int n = n0 + tx*4 + (j&3) + ((j>>2)<<6);
            float v = acc[i][j]*alpha;
            if (bias)   v += bias[n];
            if (addMat) v += addMat[(size_t)m*N + n];
            if (doRelu) v = fmaxf(v, 0.f);
            C[(size_t)m*N + n] = v;
        }
    }
}

__global__ void splitk_reduce(int S, int MN, const float* __restrict__ part,
                              float* __restrict__ C)
{
    int idx = blockIdx.x*256 + threadIdx.x;
    if (idx >= MN) return;
    float s = 0.f;
    #pragma unroll 4
    for (int z=0; z<S; z++) s += part[(size_t)z*MN + idx];
    C[idx] = s;
}

// ------------- streamed Gram stats via tf32 mma: G = (A*sa)(B*sb)^T ---------
// 128x128 tile, 8 warps (4 m-dir x 2 n-dir), warp = 32x64 via 2x8 m16n8k8 mma.
// Emits per-block column |.| sums (deterministic tree) and/or global max.
__global__ void __launch_bounds__(256)
gram_tf32(int Cc,
          const float* __restrict__ A, int lda, const float* __restrict__ sa,
          const float* __restrict__ Bm, int ldb, const float* __restrict__ sb,
          float* __restrict__ colAbsPart, unsigned int* __restrict__ maxOrd)
{
    __shared__ unsigned As[2][8][GPAD];
    __shared__ unsigned Bs[2][8][GPAD];
    __shared__ float cw[8][64];
    const int tid  = threadIdx.x;
    const int lane = tid & 31, wid = tid >> 5;
    const int wm = wid & 3, wn = wid >> 2;       // warp tile: rows wm*32, cols wn*64
    const int m0 = blockIdx.x * 128;             // cols (Bm rows)
    const int n0 = blockIdx.y * 128;             // rows (A rows)
    const int lr = tid >> 1, lc4 = (tid & 1) * 4;
    const int r = lane >> 2, c = lane & 3;

    float acc[2][8][4];
    #pragma unroll
    for (int mf=0; mf<2; mf++)
        #pragma unroll
        for (int nf=0; nf<8; nf++)
            #pragma unroll
            for (int q=0; q<4; q++) acc[mf][nf][q] = 0.f;

    float4 va, vb;
    auto ldg = [&](int cc) {
        va = *(const float4*)(A  + (size_t)(n0+lr)*lda + cc + lc4);
        vb = *(const float4*)(Bm + (size_t)(m0+lr)*ldb + cc + lc4);
    };
    auto sts = [&](int buf, int cc) {
        float a4[4] = {va.x, va.y, va.z, va.w};
        float b4[4] = {vb.x, vb.y, vb.z, vb.w};
        #pragma unroll
        for (int i=0;i<4;i++) {
            As[buf][lc4+i][lr] = f2tf32(a4[i] * sa[cc+lc4+i]);
            Bs[buf][lc4+i][lr] = f2tf32(b4[i] * sb[cc+lc4+i]);
        }
    };

    ldg(0); sts(0, 0);
    __syncthreads();

    int buf = 0;
    for (int cc = 0; cc < Cc; cc += 8) {
        const bool nxt = (cc + 8) < Cc;
        if (nxt) ldg(cc + 8);
        unsigned af[2][4], bf[8][2];
        #pragma unroll
        for (int mf=0; mf<2; mf++) {
            int m = wm*32 + mf*16;
            af[mf][0] = As[buf][c  ][m + r];
            af[mf][1] = As[buf][c  ][m + r + 8];
            af[mf][2] = As[buf][c+4][m + r];
            af[mf][3] = As[buf][c+4][m + r + 8];
        }
        #pragma unroll
        for (int nf=0; nf<8; nf++) {
            int n = wn*64 + nf*8 + r;
            bf[nf][0] = Bs[buf][c  ][n];
            bf[nf][1] = Bs[buf][c+4][n];
        }
        #pragma unroll
        for (int mf=0; mf<2; mf++)
            #pragma unroll
            for (int nf=0; nf<8; nf++)
                mma_tf32(acc[mf][nf], af[mf], bf[nf]);
        if (nxt) {
            sts(buf^1, cc + 8);
            __syncthreads();
            buf ^= 1;
        }
    }

    // acc[mf][nf][q]: row = n0 + wm*32 + mf*16 + r + (q>=2 ? 8 : 0)
    //                 col = m0 + wn*64 + nf*8 + 2c + (q&1)
    if (colAbsPart) {
        #pragma unroll
        for (int nf=0; nf<8; nf++) {
            float s0 = fabsf(acc[0][nf][0]) + fabsf(acc[0][nf][2])
                     + fabsf(acc[1][nf][0]) + fabsf(acc[1][nf][2]);
            float s1 = fabsf(acc[0][nf][1]) + fabsf(acc[0][nf][3])
                     + fabsf(acc[1][nf][1]) + fabsf(acc[1][nf][3]);
            #pragma unroll
            for (int off=4; off<32; off<<=1) {
                s0 += __shfl_xor_sync(0xffffffffu, s0, off);
                s1 += __shfl_xor_sync(0xffffffffu, s1, off);
            }
            if (lane < 4) {
                cw[wid][nf*8 + 2*lane    ] = s0;
                cw[wid][nf*8 + 2*lane + 1] = s1;
            }
        }
        __syncthreads();
        if (tid < 128) {
            int wn2 = tid >> 6, j = tid & 63;
            float s = cw[wn2*4+0][j] + cw[wn2*4+1][j] + cw[wn2*4+2][j] + cw[wn2*4+3][j];
            colAbsPart[(size_t)blockIdx.y*NN + m0 + tid] = s;
        }
    }
    if (maxOrd) {
        float mx = -3.4e38f;
        #pragma unroll
        for (int mf=0; mf<2; mf++)
            #pragma unroll
            for (int nf=0; nf<8; nf++)
                #pragma unroll
                for (int q=0; q<4; q++) mx = fmaxf(mx, acc[mf][nf][q]);
        #pragma unroll
        for (int off=16; off; off>>=1)
            mx = fmaxf(mx, __shfl_xor_sync(0xffffffffu, mx, off));
        __shared__ float wmx[8];
        if (lane == 0) wmx[wid] = mx;
        __syncthreads();
        if (tid == 0) {
            float m2 = wmx[0];
            #pragma unroll
            for (int t=1;t<8;t++) m2 = fmaxf(m2, wmx[t]);
            atomicMax(maxOrd, ord_of_float(m2));  // max is order-independent
        }
    }
}

// ---------------- small kernels ----------------
__global__ void convbn_stats(const float* __restrict__ xr, const float* __restrict__ g,
                             const float* __restrict__ b, float* sc, float* sh)
{
    int o = blockIdx.x;
    const float* p0 = xr + (size_t)o*4096;
    const float* p1 = xr + (size_t)CHW + (size_t)o*4096;
    float s=0.f, q=0.f;
    for (int i = threadIdx.x; i < 4096; i += 256) {
        float v = p0[i]; s += v; q += v*v;
        v = p1[i];       s += v; q += v*v;
    }
    __shared__ float ss[256], sq[256];
    ss[threadIdx.x]=s; sq[threadIdx.x]=q; __syncthreads();
    for (int off=128; off; off>>=1) {
        if (threadIdx.x < off) { ss[threadIdx.x]+=ss[threadIdx.x+off]; sq[threadIdx.x]+=sq[threadIdx.x+off]; }
        __syncthreads();
    }
    if (threadIdx.x == 0) {
        float mean = ss[0]/8192.f;
        float var  = sq[0]/8192.f - mean*mean;
        float scl  = g[o]*rsqrtf(var + 1e-5f);
        sc[o] = scl; sh[o] = b[o] - mean*scl;
    }
}

__global__ void bnrelu_k(float* x, const float* sc, const float* sh) {
    int i = blockIdx.x*256 + threadIdx.x;
    int o = (i >> 12) & 255;
    x[i] = fmaxf(x[i]*sc[o] + sh[o], 0.f);
}

__global__ void pos_kernel(const float* __restrict__ x0, const float* __restrict__ mask,
                           float* __restrict__ out)
{
    int gid = blockIdx.x*256 + threadIdx.x;
    int c = gid >> 12, p = gid & 4095;
    int i = p >> 6, j = p & 63;
    const float* img = x0 + (size_t)c*4096;
    float yd = i * (511.f/63.f);
    int Y0 = min((int)yd, 511), Y1 = min(Y0+1, 511);
    float wy = yd - (float)Y0;
    float xd = j * (511.f/63.f);
    int X0 = min((int)xd, 511), X1 = min(X0+1, 511);
    float wx = xd - (float)X0;
    int Ys[2]={Y0,Y1}; float wys[2]={1.f-wy, wy};
    int Xs[2]={X0,X1}; float wxs[2]={1.f-wx, wx};
    float acc = 0.f;
    #pragma unroll
    for (int a=0;a<2;a++) {
        int Y = Ys[a];
        float yu = Y*(63.f/511.f);
        int a0 = min((int)yu, 63), a1 = min(a0+1, 63);
        float wa = yu - (float)a0;
        #pragma unroll
        for (int b=0;b<2;b++) {
            int X = Xs[b];
            float xu = X*(63.f/511.f);
            int b0 = min((int)xu, 63), b1 = min(b0+1, 63);
            float wb = xu - (float)b0;
            float v = (img[a0*64+b0]*(1.f-wb) + img[a0*64+b1]*wb)*(1.f-wa)
                    + (img[a1*64+b0]*(1.f-wb) + img[a1*64+b1]*wb)*wa;
            acc += wys[a]*wxs[b]*mask[Y*512+X]*v;
        }
    }
    out[gid] = acc;
}

__global__ void colred_part(const float* __restrict__ X, int ld, int C,
                            float* __restrict__ pS, float* __restrict__ pQ)
{
    int r0 = blockIdx.x * (NN/CRP);       // 16 rows per block
    int c0 = threadIdx.x, c1 = threadIdx.x + 256;
    float s0=0,q0=0,s1=0,q1=0;
    #pragma unroll 4
    for (int r=0;r<NN/CRP;r++) {
        const float* row = X + (size_t)(r0+r)*ld;
        float v = row[c0]; s0 += v; q0 += v*v;
        if (C > 256) { float w = row[c1]; s1 += w; q1 += w*w; }
    }
    pS[blockIdx.x*C + c0] = s0; pQ[blockIdx.x*C + c0] = q0;
    if (C > 256) { pS[blockIdx.x*C + c1] = s1; pQ[blockIdx.x*C + c1] = q1; }
}

// mode 0: o1=1/max(||col||,eps), o2=o1^2.  mode 1: BN scale/shift over 4096 rows.
__global__ void colred_fin(const float* __restrict__ pS, const float* __restrict__ pQ,
                           int C, int mode,
                           const float* g, const float* b, float* o1, float* o2)
{
    int c = blockIdx.x*256 + threadIdx.x;
    if (c >= C) return;
    float S=0.f, Q=0.f;
    #pragma unroll 4
    for (int z=0; z<CRP; z++) { S += pS[z*C+c]; Q += pQ[z*C+c]; }
    if (mode == 0) {
        float inv = 1.f / fmaxf(sqrtf(Q), 1e-12f);
        o1[c] = inv; o2[c] = inv*inv;
    } else {
        float mean = S*(1.f/4096.f);
        float var  = Q*(1.f/4096.f) - mean*mean;
        float sc   = g[c]*rsqrtf(var + 1e-5f);
        o1[c] = sc; o2[c] = b[c] - mean*sc;
    }
}

__global__ void colabs_fin(const float* __restrict__ part, float* __restrict__ inv) {
    int m = blockIdx.x*256 + threadIdx.x;
    float s = 0.f;
    #pragma unroll 4
    for (int z=0; z<32; z++) s += part[z*NN + m];
    inv[m] = 1.f / fmaxf(s, 1e-12f);
}

__global__ void vecmul_k(const float* a, const float* b, float* o) {
    int i = blockIdx.x*256 + threadIdx.x;
    o[i] = a[i]*b[i];
}

__global__ void init_rmax_k(unsigned int* p) { *p = 0u; }
__global__ void fin_rmax_k(const unsigned int* p, float* o) {
    unsigned u = *p;
    unsigned f = (u & 0x80000000u) ? (u & 0x7fffffffu) : ~u;
    *o = 1.f / __uint_as_float(f);
}

__global__ void bnapply_k(const float* y, const float* sc, const float* sh, float* o) {
    int i = blockIdx.x*256 + threadIdx.x;
    int c = i & 511;
    o[i] = fmaxf(y[i]*sc[c] + sh[c], 0.f);
}

// ---------------- host ----------------
#define SYMF(name, sym) float* name; { void* _p=nullptr; cudaGetSymbolAddress(&_p, sym); name=(float*)_p; }

extern "C" void kernel_launch(void* const* d_in, const int* in_sizes, int n_in,
                              void* d_out, int out_size)
{
    const float* x      = (const float*)d_in[0];
    const float* mask   = (const float*)d_in[1];
    const float* conv1w = (const float*)d_in[2];
    const float* bn1g   = (const float*)d_in[3];
    const float* bn1b   = (const float*)d_in[4];
    const float* g0aw   = (const float*)d_in[5];
    const float* g0ab   = (const float*)d_in[6];
    const float* g0uw   = (const float*)d_in[7];
    const float* g0ub   = (const float*)d_in[8];
    const float* g1aw   = (const float*)d_in[9];
    const float* g1ab   = (const float*)d_in[10];
    const float* g1uw   = (const float*)d_in[11];
    const float* g1ub   = (const float*)d_in[12];
    const float* cgw    = (const float*)d_in[13];
    const float* cgb    = (const float*)d_in[14];
    const float* cgbng  = (const float*)d_in[15];
    const float* cgbnb  = (const float*)d_in[16];
    float* out = (float*)d_out;

    SYMF(xr, g_xr)       SYMF(pos, g_pos)
    SYMF(bnsc, g_bnsc)   SYMF(bnsh, g_bnsh)
    SYMF(pS, g_partS)    SYMF(pQ, g_partQ)
    SYMF(invn_s, g_invn_s)   SYMF(invn2_s, g_invn2_s)
    SYMF(invn_q, g_invn_q)   SYMF(invn2_q, g_invn2_q)
    SYMF(invn_e1, g_invn_e1) SYMF(dum1, g_dummy1)
    SYMF(invn_e2, g_invn_e2) SYMF(dum2, g_dummy2)
    SYMF(invee, g_invee)
    SYMF(fsc, g_fsc)     SYMF(fsh, g_fsh)
    SYMF(cap, g_colabsPart)
    SYMF(invcol_s, g_invcol_s) SYMF(invcol_q, g_invcol_q)
    SYMF(ax, g_ax)       SYMF(ux, g_ux)
    SYMF(T, g_T)         SYMF(Tp, g_Tpart)
    SYMF(e1, g_emb1)     SYMF(e2, g_emb2)
    SYMF(r2, g_r2)       SYMF(y2, g_y2)
    SYMF(invr, g_inv_rmax)
    unsigned int* rmo; { void* _p=nullptr; cudaGetSymbolAddress(&_p, g_rmax_ord); rmo=(unsigned int*)_p; }

    const float* xq = xr + CHW;   // x[1] after conv/bn/relu, viewed (4096,256)

    // 1) conv1: xr[b] = conv1_w @ x[b]   (M=256,N=4096,K=512) batched z=2
    gemm_k<0,0><<<dim3(32,2,2),256>>>(256,4096,512, conv1w,512,0, x,4096,(size_t)512*4096,
        xr,(size_t)CHW, nullptr,nullptr, 0, 1.f,nullptr, nullptr,nullptr,0);
    // 2) BN train stats + apply + relu
    convbn_stats<<<256,256>>>(xr, bn1g, bn1b, bnsc, bnsh);
    bnrelu_k<<<2*CHW/256,256>>>(xr, bnsc, bnsh);
    // 3) pos_node = down(up(x0)*mask)
    pos_kernel<<<CHW/256,256>>>(xr, mask, pos);
    // 4) column norms of x_s, x_q
    colred_part<<<CRP,256>>>(pos, 256, 256, pS, pQ);
    colred_fin<<<1,256>>>(pS, pQ, 256, 0, nullptr,nullptr, invn_s, invn2_s);
    colred_part<<<CRP,256>>>(xq, 256, 256, pS, pQ);
    colred_fin<<<1,256>>>(pS, pQ, 256, 0, nullptr,nullptr, invn_q, invn2_q);

    // ---- layer 0, graph s -> emb1 ----
    gemm_k<0,1><<<dim3(4,32,1),256>>>(4096,512,256, pos,256,0, g0aw,256,0, ax,0,
        nullptr,nullptr, 0, 1.f,nullptr, g0ab,nullptr,1);
    gemm_k<0,1><<<dim3(4,32,1),256>>>(4096,512,256, pos,256,0, g0uw,256,0, ux,0,
        nullptr,nullptr, 0, 1.f,nullptr, g0ub,nullptr,1);
    gram_tf32<<<dim3(32,32),256>>>(256, pos,256,invn_s, pos,256,invn_s, cap, nullptr);
    colabs_fin<<<16,256>>>(cap, invcol_s);
    gemm_k<1,0><<<dim3(4,2,16),256>>>(256,512,4096, pos,256,0, ax,512,0, Tp,0,
        nullptr,invcol_s, 256, 1.f,nullptr, nullptr,nullptr,0);
    splitk_reduce<<<512,256>>>(16, 256*512, Tp, T);
    gemm_k<0,0><<<dim3(4,32,1),256>>>(4096,512,256, pos,256,0, T,512,0, e1,0,
        invn2_s,nullptr, 0, 1.f,nullptr, nullptr,ux,0);

    // ---- layer 0, graph q -> emb2 ----
    gemm_k<0,1><<<dim3(4,32,1),256>>>(4096,512,256, xq,256,0, g0aw,256,0, ax,0,
        nullptr,nullptr, 0, 1.f,nullptr, g0ab,nullptr,1);
    gemm_k<0,1><<<dim3(4,32,1),256>>>(4096,512,256, xq,256,0, g0uw,256,0, ux,0,
        nullptr,nullptr, 0, 1.f,nullptr, g0ub,nullptr,1);
    gram_tf32<<<dim3(32,32),256>>>(256, xq,256,invn_q, xq,256,invn_q, cap, nullptr);
    colabs_fin<<<16,256>>>(cap, invcol_q);
    gemm_k<1,0><<<dim3(4,2,16),256>>>(256,512,4096, xq,256,0, ax,512,0, Tp,0,
        nullptr,invcol_q, 256, 1.f,nullptr, nullptr,nullptr,0);
    splitk_reduce<<<512,256>>>(16, 256*512, Tp, T);
    gemm_k<0,0><<<dim3(4,32,1),256>>>(4096,512,256, xq,256,0, T,512,0, e2,0,
        invn2_q,nullptr, 0, 1.f,nullptr, nullptr,ux,0);

    // ---- R = adjacency(emb1, emb2): norms + streamed max ----
    colred_part<<<CRP,256>>>(e1, 512, 512, pS, pQ);
    colred_fin<<<2,256>>>(pS, pQ, 512, 0, nullptr,nullptr, invn_e1, dum1);
    colred_part<<<CRP,256>>>(e2, 512, 512, pS, pQ);
    colred_fin<<<2,256>>>(pS, pQ, 512, 0, nullptr,nullptr, invn_e2, dum2);
    vecmul_k<<<2,256>>>(invn_e1, invn_e2, invee);
    init_rmax_k<<<1,1>>>(rmo);
    gram_tf32<<<dim3(32,32),256>>>(512, e1,512,invn_e1, e2,512,invn_e2, nullptr, rmo);
    fin_rmax_k<<<1,1>>>(rmo, invr);

    // ---- cross for emb2: r2 = (1/Rmax) * (emb2*invee) @ (emb1^T emb1) ----
    gemm_k<1,0><<<dim3(4,4,16),256>>>(512,512,4096, e1,512,0, e1,512,0, Tp,0,
        nullptr,nullptr, 256, 1.f,nullptr, nullptr,nullptr,0);
    splitk_reduce<<<1024,256>>>(16, 512*512, Tp, T);
    gemm_k<0,0><<<dim3(4,32,1),256>>>(4096,512,512, e2,512,0, T,512,0, r2,0,
        invee,nullptr, 0, 1.f,invr, nullptr,nullptr,0);
    // y = emb2 @ Wl^T + r2 @ Wr^T + cg_b   (cg_w is (512,1024))
    gemm_k<0,1><<<dim3(4,32,1),256>>>(4096,512,512, e2,512,0, cgw,1024,0, y2,0,
        nullptr,nullptr, 0, 1.f,nullptr, cgb,nullptr,0);
    gemm_k<0,1><<<dim3(4,32,1),256>>>(4096,512,512, r2,512,0, cgw+512,1024,0, y2,0,
        nullptr,nullptr, 0, 1.f,nullptr, nullptr,y2,0);
    // BN1d over nodes + relu -> emb2_new (overwrite e2)
    colred_part<<<CRP,256>>>(y2, 512, 512, pS, pQ);
    colred_fin<<<2,256>>>(pS, pQ, 512, 1, cgbng, cgbnb, fsc, fsh);
    bnapply_k<<<NN*512/256,256>>>(y2, fsc, fsh, e2);

    // ---- layer 1 for emb2 (uses A_q), writes d_out directly ----
    gemm_k<0,1><<<dim3(4,32,1),256>>>(4096,512,512, e2,512,0, g1aw,512,0, ax,0,
        nullptr,nullptr, 0, 1.f,nullptr, g1ab,nullptr,1);
    gemm_k<0,1><<<dim3(4,32,1),256>>>(4096,512,512, e2,512,0, g1uw,512,0, ux,0,
        nullptr,nullptr, 0, 1.f,nullptr, g1ub,nullptr,1);
    gemm_k<1,0><<<dim3(4,2,16),256>>>(256,512,4096, xq,256,0, ax,512,0, Tp,0,
        nullptr,invcol_q, 256, 1.f,nullptr, nullptr,nullptr,0);
    splitk_reduce<<<512,256>>>(16, 256*512, Tp, T);
    gemm_k<0,0><<<dim3(4,32,1),256>>>(4096,512,256, xq,256,0, T,512,0, out,0,
        invn2_q,nullptr, 0, 1.f,nullptr, nullptr,ux,0);
}